// round 3
// baseline (speedup 1.0000x reference)
#include <cuda_runtime.h>
#include <cuda_bf16.h>
#include <cstdint>

// Problem dims
static constexpr int MROWS = 8192;   // B*S
static constexpr int DIN   = 4096;
static constexpr int DOUT  = 4096;

// GEMM tiling (int8 path): 128-byte rows hold K=128 int8
static constexpr int BM = 128, BN = 128, BK = 128;
static constexpr int KTILES = DIN / BK;          // 32
static constexpr int STAGES = 3;
static constexpr int TILE_BYTES  = BM * BK;      // 16384 per operand
static constexpr int STAGE_BYTES = 2 * TILE_BYTES;
static constexpr int SMEM_TOTAL  = STAGES * STAGE_BYTES;  // 98304

// Quantized operands (device globals: no cudaMalloc allowed)
__device__ __align__(16) int8_t g_xq[(size_t)MROWS * DIN];  // 32 MB
__device__ __align__(16) int8_t g_wq[(size_t)DOUT * DIN];   // 16 MB

// ---------- helpers (base-sm_103-safe PTX only) ----------
__device__ __forceinline__ uint32_t smem_u32(const void* p) {
    uint32_t a;
    asm("{ .reg .u64 t; cvta.to.shared.u64 t, %1; cvt.u32.u64 %0, t; }"
        : "=r"(a) : "l"(p));
    return a;
}
// SW128: rows are 128B; XOR 16B-chunk index with row%8 -> conflict-free ldmatrix
__device__ __forceinline__ uint32_t swz(uint32_t o) { return o ^ ((o >> 3) & 0x70); }

__device__ __forceinline__ void cpasync16(uint32_t s, const void* g) {
    asm volatile("cp.async.cg.shared.global [%0], [%1], 16;" :: "r"(s), "l"(g));
}
__device__ __forceinline__ void cp_commit() {
    asm volatile("cp.async.commit_group;" ::: "memory");
}
__device__ __forceinline__ void cp_wait1() {
    asm volatile("cp.async.wait_group 1;" ::: "memory");
}
__device__ __forceinline__ void ldmx4(uint32_t* r, uint32_t addr) {
    asm volatile("ldmatrix.sync.aligned.m8n8.x4.shared.b16 {%0,%1,%2,%3}, [%4];"
                 : "=r"(r[0]), "=r"(r[1]), "=r"(r[2]), "=r"(r[3]) : "r"(addr));
}
// int8 IMMA: m16n8k32, s32 accumulate
__device__ __forceinline__ void mma_s8(int* d, const uint32_t* a, const uint32_t* b) {
    asm volatile(
        "mma.sync.aligned.m16n8k32.row.col.s32.s8.s8.s32 "
        "{%0,%1,%2,%3}, {%4,%5,%6,%7}, {%8,%9}, {%0,%1,%2,%3};"
        : "+r"(d[0]), "+r"(d[1]), "+r"(d[2]), "+r"(d[3])
        : "r"(a[0]), "r"(a[1]), "r"(a[2]), "r"(a[3]), "r"(b[0]), "r"(b[1]));
}

// ---------- quantization passes ----------
// x_int8 = trunc(x * input_scale) (toward zero == astype(int32); values fit int8)
__global__ void __launch_bounds__(256) quant_x_kernel(
    const float* __restrict__ x, const float* __restrict__ iscale) {
    size_t i = ((size_t)blockIdx.x * blockDim.x + threadIdx.x) * 8;
    float is = iscale[0];
    float4 v0 = *reinterpret_cast<const float4*>(x + i);
    float4 v1 = *reinterpret_cast<const float4*>(x + i + 4);
    int a0 = __float2int_rz(v0.x * is), a1 = __float2int_rz(v0.y * is);
    int a2 = __float2int_rz(v0.z * is), a3 = __float2int_rz(v0.w * is);
    int a4 = __float2int_rz(v1.x * is), a5 = __float2int_rz(v1.y * is);
    int a6 = __float2int_rz(v1.z * is), a7 = __float2int_rz(v1.w * is);
    uint2 u;
    u.x = (uint32_t)(a0 & 0xFF) | ((uint32_t)(a1 & 0xFF) << 8) |
          ((uint32_t)(a2 & 0xFF) << 16) | ((uint32_t)(a3 & 0xFF) << 24);
    u.y = (uint32_t)(a4 & 0xFF) | ((uint32_t)(a5 & 0xFF) << 8) |
          ((uint32_t)(a6 & 0xFF) << 16) | ((uint32_t)(a7 & 0xFF) << 24);
    *reinterpret_cast<uint2*>(g_xq + i) = u;
}

// w_int8 = wraparound(round_half_even(w * weight_scale[row]))
__global__ void __launch_bounds__(256) quant_w_kernel(
    const float* __restrict__ w, const float* __restrict__ wscale) {
    size_t i = ((size_t)blockIdx.x * blockDim.x + threadIdx.x) * 8;
    int row = (int)(i >> 12);  // / DIN
    float ws = wscale[row];
    float4 v0 = *reinterpret_cast<const float4*>(w + i);
    float4 v1 = *reinterpret_cast<const float4*>(w + i + 4);
    int a0 = __float2int_rn(v0.x * ws), a1 = __float2int_rn(v0.y * ws);
    int a2 = __float2int_rn(v0.z * ws), a3 = __float2int_rn(v0.w * ws);
    int a4 = __float2int_rn(v1.x * ws), a5 = __float2int_rn(v1.y * ws);
    int a6 = __float2int_rn(v1.z * ws), a7 = __float2int_rn(v1.w * ws);
    uint2 u;
    u.x = (uint32_t)(a0 & 0xFF) | ((uint32_t)(a1 & 0xFF) << 8) |
          ((uint32_t)(a2 & 0xFF) << 16) | ((uint32_t)(a3 & 0xFF) << 24);
    u.y = (uint32_t)(a4 & 0xFF) | ((uint32_t)(a5 & 0xFF) << 8) |
          ((uint32_t)(a6 & 0xFF) << 16) | ((uint32_t)(a7 & 0xFF) << 24);
    *reinterpret_cast<uint2*>(g_wq + i) = u;
}

// ---------- GEMM: out = (Xq @ Wq^T) * sc + bias * sc ----------
__global__ void __launch_bounds__(256) gemm_kernel(
    const float* __restrict__ bias, const float* __restrict__ wscale,
    const float* __restrict__ iscale, float* __restrict__ out) {
    extern __shared__ char smem[];
    const uint32_t sbase = smem_u32(smem);
    const int tid  = threadIdx.x;
    const int lane = tid & 31;
    const int warp = tid >> 5;
    const int wm = (warp >> 2) * 64;   // warp M offset within CTA tile
    const int wn = (warp & 3) * 32;    // warp N offset
    const int m0 = blockIdx.y * BM;
    const int n0 = blockIdx.x * BN;

    const int8_t* Abase = g_xq + (size_t)m0 * DIN;
    const int8_t* Bbase = g_wq + (size_t)n0 * DIN;

    // loader: 1024 16B chunks per operand tile / 256 threads = 4 each
    const int lrow0 = tid >> 3;        // + u*32
    const int lcol  = (tid & 7) * 16;  // byte col

    auto load_tile = [&](int kt, int stage) {
        const int8_t* Ak = Abase + kt * BK;
        const int8_t* Bk = Bbase + kt * BK;
        const uint32_t sA = sbase + stage * STAGE_BYTES;
        const uint32_t sB = sA + TILE_BYTES;
#pragma unroll
        for (int u = 0; u < 4; u++) {
            const int row = lrow0 + u * 32;
            const uint32_t so = swz((uint32_t)(row * 128 + lcol));
            cpasync16(sA + so, Ak + (size_t)row * DIN + lcol);
            cpasync16(sB + so, Bk + (size_t)row * DIN + lcol);
        }
    };

    // prologue
    load_tile(0, 0); cp_commit();
    load_tile(1, 1); cp_commit();

    int acc[4][4][4];
#pragma unroll
    for (int a = 0; a < 4; a++)
#pragma unroll
        for (int b = 0; b < 4; b++)
#pragma unroll
            for (int c = 0; c < 4; c++) acc[a][b][c] = 0;

    const int g = lane >> 3, r = lane & 7;

    for (int kt = 0; kt < KTILES; kt++) {
        cp_wait1();
        __syncthreads();
        const int buf = kt % STAGES;
        const uint32_t sA = sbase + buf * STAGE_BYTES;
        const uint32_t sB = sA + TILE_BYTES;

#pragma unroll
        for (int ks = 0; ks < BK / 32; ks++) {
            const int kb = ks * 32;  // byte col base (32 int8 per MMA)
            uint32_t afrag[4][4];
#pragma unroll
            for (int mi = 0; mi < 4; mi++) {
                const int row = wm + mi * 16 + r + ((g & 1) ? 8 : 0);
                const int col = kb + ((g & 2) ? 16 : 0);
                ldmx4(afrag[mi], sA + swz((uint32_t)(row * 128 + col)));
            }
            uint32_t bfrag[4][2];
#pragma unroll
            for (int nb = 0; nb < 2; nb++) {
                const int row = wn + nb * 16 + r + ((g & 2) ? 8 : 0);
                const int col = kb + ((g & 1) ? 16 : 0);
                uint32_t t[4];
                ldmx4(t, sB + swz((uint32_t)(row * 128 + col)));
                bfrag[nb * 2 + 0][0] = t[0]; bfrag[nb * 2 + 0][1] = t[1];
                bfrag[nb * 2 + 1][0] = t[2]; bfrag[nb * 2 + 1][1] = t[3];
            }
#pragma unroll
            for (int mi = 0; mi < 4; mi++)
#pragma unroll
                for (int ni = 0; ni < 4; ni++)
                    mma_s8(acc[mi][ni], afrag[mi], bfrag[ni]);
        }
        __syncthreads();
        if (kt + STAGES - 1 < KTILES) load_tile(kt + STAGES - 1, (kt + STAGES - 1) % STAGES);
        cp_commit();
    }

    // epilogue: dequant + bias, f32 out (acc < 2^24 -> exact int->float)
    const float is = iscale[0];
    float sc[4][2], bq[4][2];
#pragma unroll
    for (int ni = 0; ni < 4; ni++)
#pragma unroll
        for (int j = 0; j < 2; j++) {
            const int n = n0 + wn + ni * 8 + (lane & 3) * 2 + j;
            const float s = 1.0f / (wscale[n] * is);
            sc[ni][j] = s;
            bq[ni][j] = bias[n] * s;
        }
    const int mrow = m0 + wm + (lane >> 2);
    const int ncol0 = n0 + wn + (lane & 3) * 2;
#pragma unroll
    for (int mi = 0; mi < 4; mi++) {
#pragma unroll
        for (int ni = 0; ni < 4; ni++) {
            float* o0 = out + (size_t)(mrow + mi * 16) * DOUT + ncol0 + ni * 8;
            float* o1 = o0 + 8 * DOUT;
            float2 v0, v1;
            v0.x = __int2float_rn(acc[mi][ni][0]) * sc[ni][0] + bq[ni][0];
            v0.y = __int2float_rn(acc[mi][ni][1]) * sc[ni][1] + bq[ni][1];
            v1.x = __int2float_rn(acc[mi][ni][2]) * sc[ni][0] + bq[ni][0];
            v1.y = __int2float_rn(acc[mi][ni][3]) * sc[ni][1] + bq[ni][1];
            *reinterpret_cast<float2*>(o0) = v0;
            *reinterpret_cast<float2*>(o1) = v1;
        }
    }
}

// ---------- launch ----------
extern "C" void kernel_launch(void* const* d_in, const int* in_sizes, int n_in,
                              void* d_out, int out_size) {
    const float* x  = (const float*)d_in[0];
    const float* w  = (const float*)d_in[1];
    const float* bi = (const float*)d_in[2];
    const float* ws = (const float*)d_in[3];
    const float* is = (const float*)d_in[4];
    float* out = (float*)d_out;

    cudaFuncSetAttribute(gemm_kernel,
                         cudaFuncAttributeMaxDynamicSharedMemorySize, SMEM_TOTAL);

    quant_x_kernel<<<(MROWS * DIN) / (256 * 8), 256>>>(x, is);
    quant_w_kernel<<<(DOUT * DIN) / (256 * 8), 256>>>(w, ws);
    gemm_kernel<<<dim3(DOUT / BN, MROWS / BM), 256, SMEM_TOTAL>>>(bi, ws, is, out);
}

// round 4
// speedup vs baseline: 4.2387x; 4.2387x over previous
#include <cuda_runtime.h>
#include <cuda_bf16.h>
#include <cstdint>

// Problem dims
static constexpr int MROWS = 8192;   // B*S
static constexpr int DIN   = 4096;
static constexpr int DOUT  = 4096;

// GEMM tiling: BM=256, BN=128, BK=64 (bf16, 128B rows)
static constexpr int BM = 256, BN = 128, BK = 64;
static constexpr int KTILES = DIN / BK;            // 64
static constexpr int STAGES = 4;
static constexpr int A_TILE_BYTES = BM * BK * 2;   // 32768
static constexpr int B_TILE_BYTES = BN * BK * 2;   // 16384
static constexpr int STAGE_BYTES  = A_TILE_BYTES + B_TILE_BYTES;  // 49152
static constexpr int SMEM_TOTAL   = STAGES * STAGE_BYTES;         // 196608

// Quantized operands (device globals: no cudaMalloc allowed)
__device__ __nv_bfloat16 g_xq[(size_t)MROWS * DIN];  // 64 MB
__device__ __nv_bfloat16 g_wq[(size_t)DOUT * DIN];   // 32 MB

// ---------- helpers (base-sm_103-safe PTX only) ----------
__device__ __forceinline__ uint32_t smem_u32(const void* p) {
    uint32_t a;
    asm("{ .reg .u64 t; cvta.to.shared.u64 t, %1; cvt.u32.u64 %0, t; }"
        : "=r"(a) : "l"(p));
    return a;
}
// SW128: 128B rows; XOR 16B-chunk index with row%8 -> conflict-free ldmatrix
__device__ __forceinline__ uint32_t swz(uint32_t o) { return o ^ ((o >> 3) & 0x70); }

__device__ __forceinline__ void cpasync16(uint32_t s, const void* g) {
    asm volatile("cp.async.cg.shared.global [%0], [%1], 16;" :: "r"(s), "l"(g));
}
__device__ __forceinline__ void cp_commit() {
    asm volatile("cp.async.commit_group;" ::: "memory");
}
__device__ __forceinline__ void cp_wait2() {
    asm volatile("cp.async.wait_group 2;" ::: "memory");
}
__device__ __forceinline__ void ldmx4(uint32_t* r, uint32_t addr) {
    asm volatile("ldmatrix.sync.aligned.m8n8.x4.shared.b16 {%0,%1,%2,%3}, [%4];"
                 : "=r"(r[0]), "=r"(r[1]), "=r"(r[2]), "=r"(r[3]) : "r"(addr));
}
__device__ __forceinline__ void mma16816(float* d, const uint32_t* a, const uint32_t* b) {
    asm volatile(
        "mma.sync.aligned.m16n8k16.row.col.f32.bf16.bf16.f32 "
        "{%0,%1,%2,%3}, {%4,%5,%6,%7}, {%8,%9}, {%0,%1,%2,%3};"
        : "+f"(d[0]), "+f"(d[1]), "+f"(d[2]), "+f"(d[3])
        : "r"(a[0]), "r"(a[1]), "r"(a[2]), "r"(a[3]), "r"(b[0]), "r"(b[1]));
}

// ---------- quantization passes (bf16 outputs; small ints are exact) ----------
__global__ void __launch_bounds__(256) quant_x_kernel(
    const float* __restrict__ x, const float* __restrict__ iscale) {
    size_t i = ((size_t)blockIdx.x * blockDim.x + threadIdx.x) * 4;
    float is = iscale[0];
    float4 v = *reinterpret_cast<const float4*>(x + i);
    __nv_bfloat162 p0 = __floats2bfloat162_rn(truncf(v.x * is), truncf(v.y * is));
    __nv_bfloat162 p1 = __floats2bfloat162_rn(truncf(v.z * is), truncf(v.w * is));
    uint2 u;
    u.x = *reinterpret_cast<uint32_t*>(&p0);
    u.y = *reinterpret_cast<uint32_t*>(&p1);
    *reinterpret_cast<uint2*>(g_xq + i) = u;
}

__global__ void __launch_bounds__(256) quant_w_kernel(
    const float* __restrict__ w, const float* __restrict__ wscale) {
    size_t i = ((size_t)blockIdx.x * blockDim.x + threadIdx.x) * 4;
    int row = (int)(i >> 12);  // / DIN
    float ws = wscale[row];
    float4 v = *reinterpret_cast<const float4*>(w + i);
    float f0 = (float)(int8_t)__float2int_rn(v.x * ws);
    float f1 = (float)(int8_t)__float2int_rn(v.y * ws);
    float f2 = (float)(int8_t)__float2int_rn(v.z * ws);
    float f3 = (float)(int8_t)__float2int_rn(v.w * ws);
    __nv_bfloat162 p0 = __floats2bfloat162_rn(f0, f1);
    __nv_bfloat162 p1 = __floats2bfloat162_rn(f2, f3);
    uint2 u;
    u.x = *reinterpret_cast<uint32_t*>(&p0);
    u.y = *reinterpret_cast<uint32_t*>(&p1);
    *reinterpret_cast<uint2*>(g_wq + i) = u;
}

// ---------- GEMM: out = (Xq @ Wq^T) * sc + bias * sc ----------
// 8 warps: 4 in M x 2 in N, each computes 64x64
__global__ void __launch_bounds__(256, 1) gemm_kernel(
    const float* __restrict__ bias, const float* __restrict__ wscale,
    const float* __restrict__ iscale, float* __restrict__ out) {
    extern __shared__ char smem[];
    const uint32_t sbase = smem_u32(smem);
    const int tid  = threadIdx.x;
    const int lane = tid & 31;
    const int warp = tid >> 5;
    const int wm = (warp >> 1) * 64;   // 0,64,128,192
    const int wn = (warp & 1) * 64;    // 0,64
    const int m0 = blockIdx.y * BM;
    const int n0 = blockIdx.x * BN;

    const __nv_bfloat16* Abase = g_xq + (size_t)m0 * DIN;
    const __nv_bfloat16* Bbase = g_wq + (size_t)n0 * DIN;

    // loader mapping: A = 2048 chunks (8/thread), B = 1024 chunks (4/thread)
    const int lrow0 = tid >> 3;        // + u*32
    const int lcol  = (tid & 7) * 8;   // bf16 col (16B)

    auto load_tile = [&](int kt, int stage) {
        const __nv_bfloat16* Ak = Abase + kt * BK;
        const __nv_bfloat16* Bk = Bbase + kt * BK;
        const uint32_t sA = sbase + stage * STAGE_BYTES;
        const uint32_t sB = sA + A_TILE_BYTES;
#pragma unroll
        for (int u = 0; u < 8; u++) {
            const int row = lrow0 + u * 32;
            const uint32_t so = swz((uint32_t)(row * 128 + lcol * 2));
            cpasync16(sA + so, Ak + (size_t)row * DIN + lcol);
            if (u < 4) cpasync16(sB + so, Bk + (size_t)row * DIN + lcol);
        }
    };

    // prologue: prefetch 3 of 4 stages
    load_tile(0, 0); cp_commit();
    load_tile(1, 1); cp_commit();
    load_tile(2, 2); cp_commit();

    float acc[4][8][4];
#pragma unroll
    for (int a = 0; a < 4; a++)
#pragma unroll
        for (int b = 0; b < 8; b++)
#pragma unroll
            for (int c = 0; c < 4; c++) acc[a][b][c] = 0.f;

    const int g = lane >> 3, r = lane & 7;

    for (int kt = 0; kt < KTILES; kt++) {
        cp_wait2();
        __syncthreads();
        const int buf = kt % STAGES;
        const uint32_t sA = sbase + buf * STAGE_BYTES;
        const uint32_t sB = sA + A_TILE_BYTES;

#pragma unroll
        for (int ks = 0; ks < BK / 16; ks++) {
            const int kb = ks * 16;
            uint32_t afrag[4][4];
#pragma unroll
            for (int mi = 0; mi < 4; mi++) {
                const int row = wm + mi * 16 + r + ((g & 1) ? 8 : 0);
                const int col = kb + ((g & 2) ? 8 : 0);
                ldmx4(afrag[mi], sA + swz((uint32_t)(row * 128 + col * 2)));
            }
            uint32_t bfrag[8][2];
#pragma unroll
            for (int nb = 0; nb < 4; nb++) {
                const int row = wn + nb * 16 + r + ((g & 2) ? 8 : 0);
                const int col = kb + ((g & 1) ? 8 : 0);
                uint32_t t[4];
                ldmx4(t, sB + swz((uint32_t)(row * 128 + col * 2)));
                bfrag[nb * 2 + 0][0] = t[0]; bfrag[nb * 2 + 0][1] = t[1];
                bfrag[nb * 2 + 1][0] = t[2]; bfrag[nb * 2 + 1][1] = t[3];
            }
#pragma unroll
            for (int mi = 0; mi < 4; mi++)
#pragma unroll
                for (int ni = 0; ni < 8; ni++)
                    mma16816(acc[mi][ni], afrag[mi], bfrag[ni]);
        }
        __syncthreads();
        if (kt + STAGES - 1 < KTILES) load_tile(kt + STAGES - 1, (kt + STAGES - 1) % STAGES);
        cp_commit();
    }

    // epilogue: dequant + bias
    const float is = iscale[0];
    float sc[8][2], bq[8][2];
#pragma unroll
    for (int ni = 0; ni < 8; ni++)
#pragma unroll
        for (int j = 0; j < 2; j++) {
            const int n = n0 + wn + ni * 8 + (lane & 3) * 2 + j;
            const float s = 1.0f / (wscale[n] * is);
            sc[ni][j] = s;
            bq[ni][j] = bias[n] * s;
        }
    const int mrow = m0 + wm + (lane >> 2);
    const int ncol0 = n0 + wn + (lane & 3) * 2;
#pragma unroll
    for (int mi = 0; mi < 4; mi++) {
#pragma unroll
        for (int ni = 0; ni < 8; ni++) {
            float* o0 = out + (size_t)(mrow + mi * 16) * DOUT + ncol0 + ni * 8;
            float* o1 = o0 + 8 * DOUT;
            float2 v0, v1;
            v0.x = acc[mi][ni][0] * sc[ni][0] + bq[ni][0];
            v0.y = acc[mi][ni][1] * sc[ni][1] + bq[ni][1];
            v1.x = acc[mi][ni][2] * sc[ni][0] + bq[ni][0];
            v1.y = acc[mi][ni][3] * sc[ni][1] + bq[ni][1];
            *reinterpret_cast<float2*>(o0) = v0;
            *reinterpret_cast<float2*>(o1) = v1;
        }
    }
}

// ---------- launch ----------
extern "C" void kernel_launch(void* const* d_in, const int* in_sizes, int n_in,
                              void* d_out, int out_size) {
    const float* x  = (const float*)d_in[0];
    const float* w  = (const float*)d_in[1];
    const float* bi = (const float*)d_in[2];
    const float* ws = (const float*)d_in[3];
    const float* is = (const float*)d_in[4];
    float* out = (float*)d_out;

    cudaFuncSetAttribute(gemm_kernel,
                         cudaFuncAttributeMaxDynamicSharedMemorySize, SMEM_TOTAL);

    quant_x_kernel<<<(MROWS * DIN) / (256 * 4), 256>>>(x, is);
    quant_w_kernel<<<(DOUT * DIN) / (256 * 4), 256>>>(w, ws);
    gemm_kernel<<<dim3(DOUT / BN, MROWS / BM), 256, SMEM_TOTAL>>>(bi, ws, is, out);
}

// round 6
// speedup vs baseline: 4.2549x; 1.0038x over previous
#include <cuda_runtime.h>
#include <cuda_bf16.h>
#include <cstdint>

// Problem dims
static constexpr int MROWS = 8192;   // B*S
static constexpr int DIN   = 4096;
static constexpr int DOUT  = 4096;

// GEMM tiling (R2 shape: 2 CTAs/SM)
static constexpr int BM = 128, BN = 128, BK = 64;
static constexpr int KTILES = DIN / BK;          // 64
static constexpr int STAGES = 3;
static constexpr int TILE_BYTES  = BM * BK * 2;  // 16384 per operand
static constexpr int STAGE_BYTES = 2 * TILE_BYTES;
static constexpr int SMEM_TOTAL  = STAGES * STAGE_BYTES;  // 98304

// Quantized operands (device globals: no cudaMalloc allowed)
__device__ __nv_bfloat16 g_xq[(size_t)MROWS * DIN];  // 64 MB
__device__ __nv_bfloat16 g_wq[(size_t)DOUT * DIN];   // 32 MB

// ---------- helpers (base-sm_103-safe PTX only) ----------
__device__ __forceinline__ uint32_t smem_u32(const void* p) {
    uint32_t a;
    asm("{ .reg .u64 t; cvta.to.shared.u64 t, %1; cvt.u32.u64 %0, t; }"
        : "=r"(a) : "l"(p));
    return a;
}
__device__ __forceinline__ uint32_t swz(uint32_t o) { return o ^ ((o >> 3) & 0x70); }

__device__ __forceinline__ void cpasync16(uint32_t s, const void* g) {
    asm volatile("cp.async.cg.shared.global [%0], [%1], 16;" :: "r"(s), "l"(g));
}
__device__ __forceinline__ void cp_commit() {
    asm volatile("cp.async.commit_group;" ::: "memory");
}
__device__ __forceinline__ void cp_wait1() {
    asm volatile("cp.async.wait_group 1;" ::: "memory");
}
__device__ __forceinline__ void ldmx4(uint32_t* r, uint32_t addr) {
    asm volatile("ldmatrix.sync.aligned.m8n8.x4.shared.b16 {%0,%1,%2,%3}, [%4];"
                 : "=r"(r[0]), "=r"(r[1]), "=r"(r[2]), "=r"(r[3]) : "r"(addr));
}
__device__ __forceinline__ void mma16816(float* d, const uint32_t* a, const uint32_t* b) {
    asm volatile(
        "mma.sync.aligned.m16n8k16.row.col.f32.bf16.bf16.f32 "
        "{%0,%1,%2,%3}, {%4,%5,%6,%7}, {%8,%9}, {%0,%1,%2,%3};"
        : "+f"(d[0]), "+f"(d[1]), "+f"(d[2]), "+f"(d[3])
        : "r"(a[0]), "r"(a[1]), "r"(a[2]), "r"(a[3]), "r"(b[0]), "r"(b[1]));
}

// ---------- fused quantization pass ----------
static constexpr size_t NX  = (size_t)MROWS * DIN;
static constexpr size_t NW  = (size_t)DOUT * DIN;
static constexpr size_t NXV = NX / 4;
static constexpr size_t NWV = NW / 4;

__global__ void __launch_bounds__(256) quant_kernel(
    const float* __restrict__ x, const float* __restrict__ w,
    const float* __restrict__ wscale, const float* __restrict__ iscale) {
    size_t v = (size_t)blockIdx.x * blockDim.x + threadIdx.x;
    if (v < NXV) {
        const size_t i = v * 4;
        const float is = iscale[0];
        float4 t = *reinterpret_cast<const float4*>(x + i);
        __nv_bfloat162 p0 = __floats2bfloat162_rn(truncf(t.x * is), truncf(t.y * is));
        __nv_bfloat162 p1 = __floats2bfloat162_rn(truncf(t.z * is), truncf(t.w * is));
        uint2 u;
        u.x = *reinterpret_cast<uint32_t*>(&p0);
        u.y = *reinterpret_cast<uint32_t*>(&p1);
        *reinterpret_cast<uint2*>(g_xq + i) = u;
    } else if (v < NXV + NWV) {
        const size_t i = (v - NXV) * 4;
        const int row = (int)(i >> 12);  // / DIN
        const float ws = wscale[row];
        float4 t = *reinterpret_cast<const float4*>(w + i);
        float f0 = (float)(int8_t)__float2int_rn(t.x * ws);
        float f1 = (float)(int8_t)__float2int_rn(t.y * ws);
        float f2 = (float)(int8_t)__float2int_rn(t.z * ws);
        float f3 = (float)(int8_t)__float2int_rn(t.w * ws);
        __nv_bfloat162 p0 = __floats2bfloat162_rn(f0, f1);
        __nv_bfloat162 p1 = __floats2bfloat162_rn(f2, f3);
        uint2 u;
        u.x = *reinterpret_cast<uint32_t*>(&p0);
        u.y = *reinterpret_cast<uint32_t*>(&p1);
        *reinterpret_cast<uint2*>(g_wq + i) = u;
    }
}

// ---------- GEMM: out = (Xq @ Wq^T) * sc + bias * sc ----------
__global__ void __launch_bounds__(256, 2) gemm_kernel(
    const float* __restrict__ bias, const float* __restrict__ wscale,
    const float* __restrict__ iscale, float* __restrict__ out) {
    extern __shared__ char smem[];
    const uint32_t sbase = smem_u32(smem);
    const int tid  = threadIdx.x;
    const int lane = tid & 31;
    const int warp = tid >> 5;
    const int wm = (warp >> 2) * 64;
    const int wn = (warp & 3) * 32;
    const int m0 = blockIdx.y * BM;
    const int n0 = blockIdx.x * BN;

    // Hoisted loader addressing
    const int lrow0 = tid >> 3;
    const int lcol  = (tid & 7) * 8;
    uint32_t soff[4];
    const __nv_bfloat16* aptr[4];
    const __nv_bfloat16* bptr[4];
#pragma unroll
    for (int u = 0; u < 4; u++) {
        const int row = lrow0 + u * 32;
        soff[u] = swz((uint32_t)(row * 128 + lcol * 2));
        aptr[u] = g_xq + (size_t)(m0 + row) * DIN + lcol;
        bptr[u] = g_wq + (size_t)(n0 + row) * DIN + lcol;
    }

    auto load_tile = [&](int kt, int stage) {
        const uint32_t sA = sbase + stage * STAGE_BYTES;
        const uint32_t sB = sA + TILE_BYTES;
        const int ko = kt * BK;
#pragma unroll
        for (int u = 0; u < 4; u++) {
            cpasync16(sA + soff[u], aptr[u] + ko);
            cpasync16(sB + soff[u], bptr[u] + ko);
        }
    };

    // prologue
    load_tile(0, 0); cp_commit();
    load_tile(1, 1); cp_commit();

    float acc[4][4][4];
#pragma unroll
    for (int a = 0; a < 4; a++)
#pragma unroll
        for (int b = 0; b < 4; b++)
#pragma unroll
            for (int c = 0; c < 4; c++) acc[a][b][c] = 0.f;

    const int g = lane >> 3, r = lane & 7;
    // Pre-swizzle base row bytes (column added inside swz per ks)
    uint32_t arow[4], brow[2];
#pragma unroll
    for (int mi = 0; mi < 4; mi++)
        arow[mi] = (uint32_t)((wm + mi * 16 + r + ((g & 1) ? 8 : 0)) * 128 +
                              (((g & 2) ? 8 : 0) * 2));
#pragma unroll
    for (int nb = 0; nb < 2; nb++)
        brow[nb] = (uint32_t)((wn + nb * 16 + r + ((g & 2) ? 8 : 0)) * 128 +
                              (((g & 1) ? 8 : 0) * 2));

    for (int kt = 0; kt < KTILES; kt++) {
        cp_wait1();
        __syncthreads();
        // next loads first: buffer (kt+2)%3 == (kt-1)%3, free once all warps
        // passed the sync (they finished computing kt-1 before it).
        if (kt + 2 < KTILES) load_tile(kt + 2, (kt + 2) % STAGES);
        cp_commit();

        const uint32_t sA = sbase + (kt % STAGES) * STAGE_BYTES;
        const uint32_t sB = sA + TILE_BYTES;
#pragma unroll
        for (int ks = 0; ks < BK / 16; ks++) {
            const uint32_t kbo = (uint32_t)(ks * 32);  // 16 bf16 = 32 bytes
            uint32_t afrag[4][4];
#pragma unroll
            for (int mi = 0; mi < 4; mi++)
                ldmx4(afrag[mi], sA + swz(arow[mi] + kbo));
            uint32_t bfrag[4][2];
#pragma unroll
            for (int nb = 0; nb < 2; nb++) {
                uint32_t t[4];
                ldmx4(t, sB + swz(brow[nb] + kbo));
                bfrag[nb * 2 + 0][0] = t[0]; bfrag[nb * 2 + 0][1] = t[1];
                bfrag[nb * 2 + 1][0] = t[2]; bfrag[nb * 2 + 1][1] = t[3];
            }
#pragma unroll
            for (int mi = 0; mi < 4; mi++)
#pragma unroll
                for (int ni = 0; ni < 4; ni++)
                    mma16816(acc[mi][ni], afrag[mi], bfrag[ni]);
        }
    }

    // epilogue
    const float is = iscale[0];
    float sc[4][2], bq[4][2];
#pragma unroll
    for (int ni = 0; ni < 4; ni++)
#pragma unroll
        for (int j = 0; j < 2; j++) {
            const int n = n0 + wn + ni * 8 + (lane & 3) * 2 + j;
            const float s = 1.0f / (wscale[n] * is);
            sc[ni][j] = s;
            bq[ni][j] = bias[n] * s;
        }
    const int mrow = m0 + wm + (lane >> 2);
    const int ncol0 = n0 + wn + (lane & 3) * 2;
#pragma unroll
    for (int mi = 0; mi < 4; mi++) {
#pragma unroll
        for (int ni = 0; ni < 4; ni++) {
            float* o0 = out + (size_t)(mrow + mi * 16) * DOUT + ncol0 + ni * 8;
            float* o1 = o0 + 8 * DOUT;
            float2 v0, v1;
            v0.x = acc[mi][ni][0] * sc[ni][0] + bq[ni][0];
            v0.y = acc[mi][ni][1] * sc[ni][1] + bq[ni][1];
            v1.x = acc[mi][ni][2] * sc[ni][0] + bq[ni][0];
            v1.y = acc[mi][ni][3] * sc[ni][1] + bq[ni][1];
            *reinterpret_cast<float2*>(o0) = v0;
            *reinterpret_cast<float2*>(o1) = v1;
        }
    }
}

// ---------- launch ----------
extern "C" void kernel_launch(void* const* d_in, const int* in_sizes, int n_in,
                              void* d_out, int out_size) {
    const float* x  = (const float*)d_in[0];
    const float* w  = (const float*)d_in[1];
    const float* bi = (const float*)d_in[2];
    const float* ws = (const float*)d_in[3];
    const float* is = (const float*)d_in[4];
    float* out = (float*)d_out;

    cudaFuncSetAttribute(gemm_kernel,
                         cudaFuncAttributeMaxDynamicSharedMemorySize, SMEM_TOTAL);

    const size_t nvec = NXV + NWV;
    quant_kernel<<<(unsigned)((nvec + 255) / 256), 256>>>(x, w, ws, is);
    gemm_kernel<<<dim3(DOUT / BN, MROWS / BM), 256, SMEM_TOTAL>>>(bi, ws, is, out);
}

// round 7
// speedup vs baseline: 4.5662x; 1.0732x over previous
#include <cuda_runtime.h>
#include <cuda_bf16.h>
#include <cstdint>

// Problem dims
static constexpr int MROWS = 8192;   // B*S
static constexpr int DIN   = 4096;
static constexpr int DOUT  = 4096;

// GEMM tiling (2 CTAs/SM)
static constexpr int BM = 128, BN = 128, BK = 64;
static constexpr int KTILES = DIN / BK;          // 64
static constexpr int STAGES = 3;
static constexpr int TILE_BYTES  = BM * BK * 2;  // 16384 per operand
static constexpr int STAGE_BYTES = 2 * TILE_BYTES;
static constexpr int SMEM_TOTAL  = STAGES * STAGE_BYTES;  // 98304

// Quantized operands (device globals: no cudaMalloc allowed)
__device__ __nv_bfloat16 g_xq[(size_t)MROWS * DIN];  // 64 MB
__device__ __nv_bfloat16 g_wq[(size_t)DOUT * DIN];   // 32 MB

// ---------- helpers (base-sm_103-safe PTX only) ----------
__device__ __forceinline__ uint32_t smem_u32(const void* p) {
    uint32_t a;
    asm("{ .reg .u64 t; cvta.to.shared.u64 t, %1; cvt.u32.u64 %0, t; }"
        : "=r"(a) : "l"(p));
    return a;
}
__device__ __forceinline__ uint32_t swz(uint32_t o) { return o ^ ((o >> 3) & 0x70); }

__device__ __forceinline__ void cpasync16(uint32_t s, const void* g) {
    asm volatile("cp.async.cg.shared.global [%0], [%1], 16;" :: "r"(s), "l"(g));
}
__device__ __forceinline__ void cp_commit() {
    asm volatile("cp.async.commit_group;" ::: "memory");
}
__device__ __forceinline__ void cp_wait1() {
    asm volatile("cp.async.wait_group 1;" ::: "memory");
}
__device__ __forceinline__ void ldmx4(uint32_t* r, uint32_t addr) {
    asm volatile("ldmatrix.sync.aligned.m8n8.x4.shared.b16 {%0,%1,%2,%3}, [%4];"
                 : "=r"(r[0]), "=r"(r[1]), "=r"(r[2]), "=r"(r[3]) : "r"(addr));
}
__device__ __forceinline__ void mma16816(float* d, const uint32_t* a, const uint32_t* b) {
    asm volatile(
        "mma.sync.aligned.m16n8k16.row.col.f32.bf16.bf16.f32 "
        "{%0,%1,%2,%3}, {%4,%5,%6,%7}, {%8,%9}, {%0,%1,%2,%3};"
        : "+f"(d[0]), "+f"(d[1]), "+f"(d[2]), "+f"(d[3])
        : "r"(a[0]), "r"(a[1]), "r"(a[2]), "r"(a[3]), "r"(b[0]), "r"(b[1]));
}

// ---------- fused quantization pass ----------
static constexpr size_t NX  = (size_t)MROWS * DIN;
static constexpr size_t NW  = (size_t)DOUT * DIN;
static constexpr size_t NXV = NX / 4;
static constexpr size_t NWV = NW / 4;

__global__ void __launch_bounds__(256) quant_kernel(
    const float* __restrict__ x, const float* __restrict__ w,
    const float* __restrict__ wscale, const float* __restrict__ iscale) {
    size_t v = (size_t)blockIdx.x * blockDim.x + threadIdx.x;
    if (v < NXV) {
        const size_t i = v * 4;
        const float is = iscale[0];
        float4 t = *reinterpret_cast<const float4*>(x + i);
        __nv_bfloat162 p0 = __floats2bfloat162_rn(truncf(t.x * is), truncf(t.y * is));
        __nv_bfloat162 p1 = __floats2bfloat162_rn(truncf(t.z * is), truncf(t.w * is));
        uint2 u;
        u.x = *reinterpret_cast<uint32_t*>(&p0);
        u.y = *reinterpret_cast<uint32_t*>(&p1);
        *reinterpret_cast<uint2*>(g_xq + i) = u;
    } else if (v < NXV + NWV) {
        const size_t i = (v - NXV) * 4;
        const int row = (int)(i >> 12);  // / DIN
        const float ws = wscale[row];
        float4 t = *reinterpret_cast<const float4*>(w + i);
        float f0 = (float)(int8_t)__float2int_rn(t.x * ws);
        float f1 = (float)(int8_t)__float2int_rn(t.y * ws);
        float f2 = (float)(int8_t)__float2int_rn(t.z * ws);
        float f3 = (float)(int8_t)__float2int_rn(t.w * ws);
        __nv_bfloat162 p0 = __floats2bfloat162_rn(f0, f1);
        __nv_bfloat162 p1 = __floats2bfloat162_rn(f2, f3);
        uint2 u;
        u.x = *reinterpret_cast<uint32_t*>(&p0);
        u.y = *reinterpret_cast<uint32_t*>(&p1);
        *reinterpret_cast<uint2*>(g_wq + i) = u;
    }
}

// ---------- GEMM: out = (Xq @ Wq^T) * sc + bias * sc ----------
__global__ void __launch_bounds__(256, 2) gemm_kernel(
    const float* __restrict__ bias, const float* __restrict__ wscale,
    const float* __restrict__ iscale, float* __restrict__ out) {
    extern __shared__ char smem[];
    const uint32_t sbase = smem_u32(smem);
    const int tid  = threadIdx.x;
    const int lane = tid & 31;
    const int warp = tid >> 5;
    const int wm = (warp >> 2) * 64;
    const int wn = (warp & 3) * 32;
    const int m0 = blockIdx.y * BM;
    const int n0 = blockIdx.x * BN;

    // Hoisted loader addressing
    const int lrow0 = tid >> 3;
    const int lcol  = (tid & 7) * 8;
    uint32_t soff[4];
    const __nv_bfloat16* aptr[4];
    const __nv_bfloat16* bptr[4];
#pragma unroll
    for (int u = 0; u < 4; u++) {
        const int row = lrow0 + u * 32;
        soff[u] = swz((uint32_t)(row * 128 + lcol * 2));
        aptr[u] = g_xq + (size_t)(m0 + row) * DIN + lcol;
        bptr[u] = g_wq + (size_t)(n0 + row) * DIN + lcol;
    }

    auto load_tile = [&](int kt, uint32_t sA) {
        const uint32_t sB = sA + TILE_BYTES;
        const int ko = kt * BK;
#pragma unroll
        for (int u = 0; u < 4; u++) {
            cpasync16(sA + soff[u], aptr[u] + ko);
            cpasync16(sB + soff[u], bptr[u] + ko);
        }
    };

    // prologue: stages 0 and 1
    load_tile(0, sbase); cp_commit();
    load_tile(1, sbase + STAGE_BYTES); cp_commit();

    float acc[4][4][4];
#pragma unroll
    for (int a = 0; a < 4; a++)
#pragma unroll
        for (int b = 0; b < 4; b++)
#pragma unroll
            for (int c = 0; c < 4; c++) acc[a][b][c] = 0.f;

    const int g = lane >> 3, r = lane & 7;
    // Base row-byte offsets (swizzle applied per-ks; column add interacts with XOR bits)
    uint32_t arow[4], brow[2];
#pragma unroll
    for (int mi = 0; mi < 4; mi++)
        arow[mi] = (uint32_t)((wm + mi * 16 + r + ((g & 1) ? 8 : 0)) * 128 +
                              (((g & 2) ? 8 : 0) * 2));
#pragma unroll
    for (int nb = 0; nb < 2; nb++)
        brow[nb] = (uint32_t)((wn + nb * 16 + r + ((g & 2) ? 8 : 0)) * 128 +
                              (((g & 1) ? 8 : 0) * 2));

    // Register-rotated stage pointers: cs = compute stage, ls = load stage
    // At iter kt: compute stage kt%3; load targets (kt+2)%3 == (kt-1)%3 == prev cs.
    const uint32_t slast = sbase + 2 * STAGE_BYTES;
    uint32_t cs = sbase;
    uint32_t ls = slast;

    for (int kt = 0; kt < KTILES; kt++) {
        cp_wait1();
        __syncthreads();
        if (kt + 2 < KTILES) load_tile(kt + 2, ls);
        cp_commit();

        const uint32_t sA = cs;
        const uint32_t sB = cs + TILE_BYTES;
#pragma unroll
        for (int ks = 0; ks < BK / 16; ks++) {
            const uint32_t kbo = (uint32_t)(ks * 32);  // 16 bf16 = 32 bytes
            // B fragments first (shared across all mi)
            uint32_t bfrag[4][2];
#pragma unroll
            for (int nb = 0; nb < 2; nb++) {
                uint32_t t[4];
                ldmx4(t, sB + swz(brow[nb] + kbo));
                bfrag[nb * 2 + 0][0] = t[0]; bfrag[nb * 2 + 0][1] = t[1];
                bfrag[nb * 2 + 1][0] = t[2]; bfrag[nb * 2 + 1][1] = t[3];
            }
            // A fragment ping-pong: prefetch mi+1 while issuing MMAs of mi
            uint32_t af[2][4];
            ldmx4(af[0], sA + swz(arow[0] + kbo));
#pragma unroll
            for (int mi = 0; mi < 4; mi++) {
                if (mi < 3) ldmx4(af[(mi + 1) & 1], sA + swz(arow[mi + 1] + kbo));
#pragma unroll
                for (int ni = 0; ni < 4; ni++)
                    mma16816(acc[mi][ni], af[mi & 1], bfrag[ni]);
            }
        }
        // rotate stages
        ls = cs;
        cs = (cs == slast) ? sbase : cs + STAGE_BYTES;
    }

    // epilogue
    const float is = iscale[0];
    float sc[4][2], bq[4][2];
#pragma unroll
    for (int ni = 0; ni < 4; ni++)
#pragma unroll
        for (int j = 0; j < 2; j++) {
            const int n = n0 + wn + ni * 8 + (lane & 3) * 2 + j;
            const float s = 1.0f / (wscale[n] * is);
            sc[ni][j] = s;
            bq[ni][j] = bias[n] * s;
        }
    const int mrow = m0 + wm + (lane >> 2);
    const int ncol0 = n0 + wn + (lane & 3) * 2;
#pragma unroll
    for (int mi = 0; mi < 4; mi++) {
#pragma unroll
        for (int ni = 0; ni < 4; ni++) {
            float* o0 = out + (size_t)(mrow + mi * 16) * DOUT + ncol0 + ni * 8;
            float* o1 = o0 + 8 * DOUT;
            float2 v0, v1;
            v0.x = acc[mi][ni][0] * sc[ni][0] + bq[ni][0];
            v0.y = acc[mi][ni][1] * sc[ni][1] + bq[ni][1];
            v1.x = acc[mi][ni][2] * sc[ni][0] + bq[ni][0];
            v1.y = acc[mi][ni][3] * sc[ni][1] + bq[ni][1];
            *reinterpret_cast<float2*>(o0) = v0;
            *reinterpret_cast<float2*>(o1) = v1;
        }
    }
}

// ---------- launch ----------
extern "C" void kernel_launch(void* const* d_in, const int* in_sizes, int n_in,
                              void* d_out, int out_size) {
    const float* x  = (const float*)d_in[0];
    const float* w  = (const float*)d_in[1];
    const float* bi = (const float*)d_in[2];
    const float* ws = (const float*)d_in[3];
    const float* is = (const float*)d_in[4];
    float* out = (float*)d_out;

    cudaFuncSetAttribute(gemm_kernel,
                         cudaFuncAttributeMaxDynamicSharedMemorySize, SMEM_TOTAL);

    const size_t nvec = NXV + NWV;
    quant_kernel<<<(unsigned)((nvec + 255) / 256), 256>>>(x, w, ws, is);
    gemm_kernel<<<dim3(DOUT / BN, MROWS / BM), 256, SMEM_TOTAL>>>(bi, ws, is, out);
}

// round 8
// speedup vs baseline: 5.0710x; 1.1106x over previous
#include <cuda_runtime.h>
#include <cuda_bf16.h>
#include <cstdint>

// Problem dims
static constexpr int MROWS = 8192;   // B*S
static constexpr int DIN   = 4096;
static constexpr int DOUT  = 4096;

// GEMM tiling (2 CTAs/SM)
static constexpr int BM = 128, BN = 128, BK = 64;
static constexpr int KTILES = DIN / BK;          // 64
static constexpr int STAGES = 3;
static constexpr int TILE_BYTES  = BM * BK * 2;  // 16384 per operand
static constexpr int STAGE_BYTES = 2 * TILE_BYTES;
static constexpr int SMEM_TOTAL  = STAGES * STAGE_BYTES;  // 98304

// Quantized operands (device globals: no cudaMalloc allowed)
__device__ __nv_bfloat16 g_xq[(size_t)MROWS * DIN];  // 64 MB
__device__ __nv_bfloat16 g_wq[(size_t)DOUT * DIN];   // 32 MB

// ---------- helpers (base-sm_103-safe PTX only) ----------
__device__ __forceinline__ uint32_t smem_u32(const void* p) {
    uint32_t a;
    asm("{ .reg .u64 t; cvta.to.shared.u64 t, %1; cvt.u32.u64 %0, t; }"
        : "=r"(a) : "l"(p));
    return a;
}
__device__ __forceinline__ uint32_t swz(uint32_t o) { return o ^ ((o >> 3) & 0x70); }

__device__ __forceinline__ void cpasync16(uint32_t s, const void* g) {
    asm volatile("cp.async.cg.shared.global [%0], [%1], 16;" :: "r"(s), "l"(g));
}
__device__ __forceinline__ void cp_commit() {
    asm volatile("cp.async.commit_group;" ::: "memory");
}
__device__ __forceinline__ void cp_wait1() {
    asm volatile("cp.async.wait_group 1;" ::: "memory");
}
__device__ __forceinline__ void ldmx4(uint32_t* r, uint32_t addr) {
    asm volatile("ldmatrix.sync.aligned.m8n8.x4.shared.b16 {%0,%1,%2,%3}, [%4];"
                 : "=r"(r[0]), "=r"(r[1]), "=r"(r[2]), "=r"(r[3]) : "r"(addr));
}
__device__ __forceinline__ void mma16816(float* d, const uint32_t* a, const uint32_t* b) {
    asm volatile(
        "mma.sync.aligned.m16n8k16.row.col.f32.bf16.bf16.f32 "
        "{%0,%1,%2,%3}, {%4,%5,%6,%7}, {%8,%9}, {%0,%1,%2,%3};"
        : "+f"(d[0]), "+f"(d[1]), "+f"(d[2]), "+f"(d[3])
        : "r"(a[0]), "r"(a[1]), "r"(a[2]), "r"(a[3]), "r"(b[0]), "r"(b[1]));
}

// ---------- quantization passes (two kernels: R2 layout, it was faster) ----------
__global__ void __launch_bounds__(256) quant_x_kernel(
    const float* __restrict__ x, const float* __restrict__ iscale) {
    size_t i = ((size_t)blockIdx.x * blockDim.x + threadIdx.x) * 4;
    float is = iscale[0];
    float4 v = *reinterpret_cast<const float4*>(x + i);
    __nv_bfloat162 p0 = __floats2bfloat162_rn(truncf(v.x * is), truncf(v.y * is));
    __nv_bfloat162 p1 = __floats2bfloat162_rn(truncf(v.z * is), truncf(v.w * is));
    uint2 u;
    u.x = *reinterpret_cast<uint32_t*>(&p0);
    u.y = *reinterpret_cast<uint32_t*>(&p1);
    *reinterpret_cast<uint2*>(g_xq + i) = u;
}

__global__ void __launch_bounds__(256) quant_w_kernel(
    const float* __restrict__ w, const float* __restrict__ wscale) {
    size_t i = ((size_t)blockIdx.x * blockDim.x + threadIdx.x) * 4;
    int row = (int)(i >> 12);  // / DIN
    float ws = wscale[row];
    float4 v = *reinterpret_cast<const float4*>(w + i);
    float f0 = (float)(int8_t)__float2int_rn(v.x * ws);
    float f1 = (float)(int8_t)__float2int_rn(v.y * ws);
    float f2 = (float)(int8_t)__float2int_rn(v.z * ws);
    float f3 = (float)(int8_t)__float2int_rn(v.w * ws);
    __nv_bfloat162 p0 = __floats2bfloat162_rn(f0, f1);
    __nv_bfloat162 p1 = __floats2bfloat162_rn(f2, f3);
    uint2 u;
    u.x = *reinterpret_cast<uint32_t*>(&p0);
    u.y = *reinterpret_cast<uint32_t*>(&p1);
    *reinterpret_cast<uint2*>(g_wq + i) = u;
}

// ---------- GEMM: out = (Xq @ Wq^T) * sc + bias * sc ----------
__global__ void __launch_bounds__(256, 2) gemm_kernel(
    const float* __restrict__ bias, const float* __restrict__ wscale,
    const float* __restrict__ iscale, float* __restrict__ out) {
    extern __shared__ char smem[];
    const uint32_t sbase = smem_u32(smem);
    const int tid  = threadIdx.x;
    const int lane = tid & 31;
    const int warp = tid >> 5;
    const int wm = (warp >> 2) * 64;
    const int wn = (warp & 3) * 32;
    const int m0 = blockIdx.y * BM;
    const int n0 = blockIdx.x * BN;

    // Loader addressing: 2 base pointers, constant row offsets (register-lean)
    const int lrow0 = tid >> 3;
    const int lcol  = (tid & 7) * 8;
    const __nv_bfloat16* abase = g_xq + (size_t)(m0 + lrow0) * DIN + lcol;
    const __nv_bfloat16* bbase = g_wq + (size_t)(n0 + lrow0) * DIN + lcol;
    uint32_t soff[4];
#pragma unroll
    for (int u = 0; u < 4; u++)
        soff[u] = swz((uint32_t)((lrow0 + u * 32) * 128 + lcol * 2)) -
                  (uint32_t)(lrow0 * 128);  // keep per-u delta; add lrow0*128 back
    // simpler: store absolute offsets
#pragma unroll
    for (int u = 0; u < 4; u++)
        soff[u] = swz((uint32_t)((lrow0 + u * 32) * 128 + lcol * 2));

    auto load_tile = [&](int kt, uint32_t sA) {
        const uint32_t sB = sA + TILE_BYTES;
        const __nv_bfloat16* a0 = abase + (size_t)kt * BK;
        const __nv_bfloat16* b0 = bbase + (size_t)kt * BK;
#pragma unroll
        for (int u = 0; u < 4; u++) {
            cpasync16(sA + soff[u], a0 + (size_t)u * 32 * DIN);
            cpasync16(sB + soff[u], b0 + (size_t)u * 32 * DIN);
        }
    };

    float acc[4][4][4];
#pragma unroll
    for (int a = 0; a < 4; a++)
#pragma unroll
        for (int b = 0; b < 4; b++)
#pragma unroll
            for (int c = 0; c < 4; c++) acc[a][b][c] = 0.f;

    const int g = lane >> 3, r = lane & 7;
    uint32_t arow[4], brow[2];
#pragma unroll
    for (int mi = 0; mi < 4; mi++)
        arow[mi] = (uint32_t)((wm + mi * 16 + r + ((g & 1) ? 8 : 0)) * 128 +
                              (((g & 2) ? 8 : 0) * 2));
#pragma unroll
    for (int nb = 0; nb < 2; nb++)
        brow[nb] = (uint32_t)((wn + nb * 16 + r + ((g & 2) ? 8 : 0)) * 128 +
                              (((g & 1) ? 8 : 0) * 2));

    uint32_t bf[2][4][2];   // double-buffered B fragments
    uint32_t af[2][4];      // A fragment ping-pong

    auto loadB = [&](uint32_t sB, uint32_t kbo, uint32_t (*dst)[2]) {
#pragma unroll
        for (int nb = 0; nb < 2; nb++) {
            uint32_t t[4];
            ldmx4(t, sB + swz(brow[nb] + kbo));
            dst[nb * 2 + 0][0] = t[0]; dst[nb * 2 + 0][1] = t[1];
            dst[nb * 2 + 1][0] = t[2]; dst[nb * 2 + 1][1] = t[3];
        }
    };

    // ---- prologue: stages 0,1 in flight; tile0 resident; frags(kt0,ks0) loaded
    load_tile(0, sbase); cp_commit();
    load_tile(1, sbase + STAGE_BYTES); cp_commit();
    cp_wait1();
    __syncthreads();
    loadB(sbase + TILE_BYTES, 0, bf[0]);
    ldmx4(af[0], sbase + swz(arow[0]));

    const uint32_t slast = sbase + 2 * STAGE_BYTES;
    uint32_t cs = sbase;   // compute stage (kt%3)
    uint32_t ls = slast;   // load stage ((kt+2)%3)

    for (int kt = 0; kt < KTILES; kt++) {
        // stage (kt+2)%3 == (kt-1)%3 is free: all warps passed last iter's sync
        if (kt + 2 < KTILES) load_tile(kt + 2, ls);
        cp_commit();

        const uint32_t sA = cs, sB = cs + TILE_BYTES;
        const uint32_t ns = (cs == slast) ? sbase : cs + STAGE_BYTES;
#pragma unroll
        for (int ks = 0; ks < 4; ks++) {
            const uint32_t kbo = (uint32_t)(ks * 32);
            const int cur = ks & 1;
#pragma unroll
            for (int mi = 0; mi < 4; mi++) {
                if (mi < 3) {
                    ldmx4(af[(mi + 1) & 1], sA + swz(arow[mi + 1] + kbo));
                } else if (ks < 3) {
                    // preload next ks: B frags + A row0
                    loadB(sB, kbo + 32, bf[cur ^ 1]);
                    ldmx4(af[0], sA + swz(arow[0] + kbo + 32));
                }
#pragma unroll
                for (int ni = 0; ni < 4; ni++)
                    mma16816(acc[mi][ni], af[mi & 1], bf[cur][ni]);
            }
        }
        // bottom of iter: make tile kt+1 visible, then preload its first frags
        cp_wait1();
        __syncthreads();
        if (kt + 1 < KTILES) {
            loadB(ns + TILE_BYTES, 0, bf[0]);
            ldmx4(af[0], ns + swz(arow[0]));
        }
        ls = cs;
        cs = ns;
    }

    // epilogue
    const float is = iscale[0];
    float sc[4][2], bq[4][2];
#pragma unroll
    for (int ni = 0; ni < 4; ni++)
#pragma unroll
        for (int j = 0; j < 2; j++) {
            const int n = n0 + wn + ni * 8 + (lane & 3) * 2 + j;
            const float s = 1.0f / (wscale[n] * is);
            sc[ni][j] = s;
            bq[ni][j] = bias[n] * s;
        }
    const int mrow = m0 + wm + (lane >> 2);
    const int ncol0 = n0 + wn + (lane & 3) * 2;
#pragma unroll
    for (int mi = 0; mi < 4; mi++) {
#pragma unroll
        for (int ni = 0; ni < 4; ni++) {
            float* o0 = out + (size_t)(mrow + mi * 16) * DOUT + ncol0 + ni * 8;
            float* o1 = o0 + 8 * DOUT;
            float2 v0, v1;
            v0.x = acc[mi][ni][0] * sc[ni][0] + bq[ni][0];
            v0.y = acc[mi][ni][1] * sc[ni][1] + bq[ni][1];
            v1.x = acc[mi][ni][2] * sc[ni][0] + bq[ni][0];
            v1.y = acc[mi][ni][3] * sc[ni][1] + bq[ni][1];
            *reinterpret_cast<float2*>(o0) = v0;
            *reinterpret_cast<float2*>(o1) = v1;
        }
    }
}

// ---------- launch ----------
extern "C" void kernel_launch(void* const* d_in, const int* in_sizes, int n_in,
                              void* d_out, int out_size) {
    const float* x  = (const float*)d_in[0];
    const float* w  = (const float*)d_in[1];
    const float* bi = (const float*)d_in[2];
    const float* ws = (const float*)d_in[3];
    const float* is = (const float*)d_in[4];
    float* out = (float*)d_out;

    cudaFuncSetAttribute(gemm_kernel,
                         cudaFuncAttributeMaxDynamicSharedMemorySize, SMEM_TOTAL);

    quant_x_kernel<<<((size_t)MROWS * DIN) / (256 * 4), 256>>>(x, is);
    quant_w_kernel<<<((size_t)DOUT * DIN) / (256 * 4), 256>>>(w, ws);
    gemm_kernel<<<dim3(DOUT / BN, MROWS / BM), 256, SMEM_TOTAL>>>(bi, ws, is, out);
}

// round 9
// speedup vs baseline: 5.1616x; 1.0179x over previous
#include <cuda_runtime.h>
#include <cuda_bf16.h>
#include <cstdint>

// Problem dims
static constexpr int MROWS = 8192;   // B*S
static constexpr int DIN   = 4096;
static constexpr int DOUT  = 4096;

// GEMM tiling (2 CTAs/SM)
static constexpr int BM = 128, BN = 128, BK = 64;
static constexpr int KTILES = DIN / BK;          // 64
static constexpr int TILE_BYTES  = BM * BK * 2;  // 16384 per operand
static constexpr int STAGE_BYTES = 2 * TILE_BYTES;
static constexpr int SMEM_TOTAL  = 3 * STAGE_BYTES;  // 98304

// Quantized operands (device globals: no cudaMalloc allowed)
__device__ __nv_bfloat16 g_xq[(size_t)MROWS * DIN];  // 64 MB
__device__ __nv_bfloat16 g_wq[(size_t)DOUT * DIN];   // 32 MB

// ---------- helpers (base-sm_103-safe PTX only) ----------
__device__ __forceinline__ uint32_t smem_u32(const void* p) {
    uint32_t a;
    asm("{ .reg .u64 t; cvta.to.shared.u64 t, %1; cvt.u32.u64 %0, t; }"
        : "=r"(a) : "l"(p));
    return a;
}
__device__ __forceinline__ uint32_t swz(uint32_t o) { return o ^ ((o >> 3) & 0x70); }

__device__ __forceinline__ void cpasync16(uint32_t s, const void* g) {
    asm volatile("cp.async.cg.shared.global [%0], [%1], 16;" :: "r"(s), "l"(g));
}
__device__ __forceinline__ void cp_commit() {
    asm volatile("cp.async.commit_group;" ::: "memory");
}
__device__ __forceinline__ void cp_wait1() {
    asm volatile("cp.async.wait_group 1;" ::: "memory");
}
__device__ __forceinline__ void ldmx4(uint32_t* r, uint32_t addr) {
    asm volatile("ldmatrix.sync.aligned.m8n8.x4.shared.b16 {%0,%1,%2,%3}, [%4];"
                 : "=r"(r[0]), "=r"(r[1]), "=r"(r[2]), "=r"(r[3]) : "r"(addr));
}
__device__ __forceinline__ void mma16816(float* d, const uint32_t* a, const uint32_t* b) {
    asm volatile(
        "mma.sync.aligned.m16n8k16.row.col.f32.bf16.bf16.f32 "
        "{%0,%1,%2,%3}, {%4,%5,%6,%7}, {%8,%9}, {%0,%1,%2,%3};"
        : "+f"(d[0]), "+f"(d[1]), "+f"(d[2]), "+f"(d[3])
        : "r"(a[0]), "r"(a[1]), "r"(a[2]), "r"(a[3]), "r"(b[0]), "r"(b[1]));
}

// ---------- fused quantization (block-level dispatch, 8 elems/thread) ----------
static constexpr size_t NX = (size_t)MROWS * DIN;   // 33.55M
static constexpr size_t NW = (size_t)DOUT * DIN;    // 16.78M
static constexpr int ELEMS_PER_BLK = 256 * 8;       // 2048
static constexpr unsigned NXB = (unsigned)(NX / ELEMS_PER_BLK);  // 16384
static constexpr unsigned NWB = (unsigned)(NW / ELEMS_PER_BLK);  // 8192

__global__ void __launch_bounds__(256) quant_kernel(
    const float* __restrict__ x, const float* __restrict__ w,
    const float* __restrict__ wscale, const float* __restrict__ iscale) {
    const unsigned b = blockIdx.x;
    if (b < NXB) {
        const size_t i = (size_t)b * ELEMS_PER_BLK + (size_t)threadIdx.x * 8;
        const float is = iscale[0];
        float4 v0 = *reinterpret_cast<const float4*>(x + i);
        float4 v1 = *reinterpret_cast<const float4*>(x + i + 4);
        __nv_bfloat162 p0 = __floats2bfloat162_rn(truncf(v0.x * is), truncf(v0.y * is));
        __nv_bfloat162 p1 = __floats2bfloat162_rn(truncf(v0.z * is), truncf(v0.w * is));
        __nv_bfloat162 p2 = __floats2bfloat162_rn(truncf(v1.x * is), truncf(v1.y * is));
        __nv_bfloat162 p3 = __floats2bfloat162_rn(truncf(v1.z * is), truncf(v1.w * is));
        uint4 u;
        u.x = *reinterpret_cast<uint32_t*>(&p0);
        u.y = *reinterpret_cast<uint32_t*>(&p1);
        u.z = *reinterpret_cast<uint32_t*>(&p2);
        u.w = *reinterpret_cast<uint32_t*>(&p3);
        *reinterpret_cast<uint4*>(g_xq + i) = u;
    } else {
        const size_t i = (size_t)(b - NXB) * ELEMS_PER_BLK + (size_t)threadIdx.x * 8;
        const int row = (int)(i >> 12);  // / DIN (8 elems never cross a row)
        const float ws = wscale[row];
        float4 v0 = *reinterpret_cast<const float4*>(w + i);
        float4 v1 = *reinterpret_cast<const float4*>(w + i + 4);
        float f0 = (float)(int8_t)__float2int_rn(v0.x * ws);
        float f1 = (float)(int8_t)__float2int_rn(v0.y * ws);
        float f2 = (float)(int8_t)__float2int_rn(v0.z * ws);
        float f3 = (float)(int8_t)__float2int_rn(v0.w * ws);
        float f4 = (float)(int8_t)__float2int_rn(v1.x * ws);
        float f5 = (float)(int8_t)__float2int_rn(v1.y * ws);
        float f6 = (float)(int8_t)__float2int_rn(v1.z * ws);
        float f7 = (float)(int8_t)__float2int_rn(v1.w * ws);
        __nv_bfloat162 p0 = __floats2bfloat162_rn(f0, f1);
        __nv_bfloat162 p1 = __floats2bfloat162_rn(f2, f3);
        __nv_bfloat162 p2 = __floats2bfloat162_rn(f4, f5);
        __nv_bfloat162 p3 = __floats2bfloat162_rn(f6, f7);
        uint4 u;
        u.x = *reinterpret_cast<uint32_t*>(&p0);
        u.y = *reinterpret_cast<uint32_t*>(&p1);
        u.z = *reinterpret_cast<uint32_t*>(&p2);
        u.w = *reinterpret_cast<uint32_t*>(&p3);
        *reinterpret_cast<uint4*>(g_wq + i) = u;
    }
}

// ---------- GEMM: out = (Xq @ Wq^T) * sc + bias * sc  (R8 winner, unchanged) ----------
__global__ void __launch_bounds__(256, 2) gemm_kernel(
    const float* __restrict__ bias, const float* __restrict__ wscale,
    const float* __restrict__ iscale, float* __restrict__ out) {
    extern __shared__ char smem[];
    const uint32_t sbase = smem_u32(smem);
    const int tid  = threadIdx.x;
    const int lane = tid & 31;
    const int warp = tid >> 5;
    const int wm = (warp >> 2) * 64;
    const int wn = (warp & 3) * 32;
    const int m0 = blockIdx.y * BM;
    const int n0 = blockIdx.x * BN;

    const int lrow0 = tid >> 3;
    const int lcol  = (tid & 7) * 8;
    const __nv_bfloat16* abase = g_xq + (size_t)(m0 + lrow0) * DIN + lcol;
    const __nv_bfloat16* bbase = g_wq + (size_t)(n0 + lrow0) * DIN + lcol;
    uint32_t soff[4];
#pragma unroll
    for (int u = 0; u < 4; u++)
        soff[u] = swz((uint32_t)((lrow0 + u * 32) * 128 + lcol * 2));

    auto load_tile = [&](int kt, uint32_t sA) {
        const uint32_t sB = sA + TILE_BYTES;
        const __nv_bfloat16* a0 = abase + (size_t)kt * BK;
        const __nv_bfloat16* b0 = bbase + (size_t)kt * BK;
#pragma unroll
        for (int u = 0; u < 4; u++) {
            cpasync16(sA + soff[u], a0 + (size_t)u * 32 * DIN);
            cpasync16(sB + soff[u], b0 + (size_t)u * 32 * DIN);
        }
    };

    float acc[4][4][4];
#pragma unroll
    for (int a = 0; a < 4; a++)
#pragma unroll
        for (int b = 0; b < 4; b++)
#pragma unroll
            for (int c = 0; c < 4; c++) acc[a][b][c] = 0.f;

    const int g = lane >> 3, r = lane & 7;
    uint32_t arow[4], brow[2];
#pragma unroll
    for (int mi = 0; mi < 4; mi++)
        arow[mi] = (uint32_t)((wm + mi * 16 + r + ((g & 1) ? 8 : 0)) * 128 +
                              (((g & 2) ? 8 : 0) * 2));
#pragma unroll
    for (int nb = 0; nb < 2; nb++)
        brow[nb] = (uint32_t)((wn + nb * 16 + r + ((g & 2) ? 8 : 0)) * 128 +
                              (((g & 1) ? 8 : 0) * 2));

    uint32_t bf[2][4][2];
    uint32_t af[2][4];

    auto loadB = [&](uint32_t sB, uint32_t kbo, uint32_t (*dst)[2]) {
#pragma unroll
        for (int nb = 0; nb < 2; nb++) {
            uint32_t t[4];
            ldmx4(t, sB + swz(brow[nb] + kbo));
            dst[nb * 2 + 0][0] = t[0]; dst[nb * 2 + 0][1] = t[1];
            dst[nb * 2 + 1][0] = t[2]; dst[nb * 2 + 1][1] = t[3];
        }
    };

    // prologue
    load_tile(0, sbase); cp_commit();
    load_tile(1, sbase + STAGE_BYTES); cp_commit();
    cp_wait1();
    __syncthreads();
    loadB(sbase + TILE_BYTES, 0, bf[0]);
    ldmx4(af[0], sbase + swz(arow[0]));

    const uint32_t slast = sbase + 2 * STAGE_BYTES;
    uint32_t cs = sbase;
    uint32_t ls = slast;

    for (int kt = 0; kt < KTILES; kt++) {
        if (kt + 2 < KTILES) load_tile(kt + 2, ls);
        cp_commit();

        const uint32_t sA = cs, sB = cs + TILE_BYTES;
        const uint32_t ns = (cs == slast) ? sbase : cs + STAGE_BYTES;
#pragma unroll
        for (int ks = 0; ks < 4; ks++) {
            const uint32_t kbo = (uint32_t)(ks * 32);
            const int cur = ks & 1;
#pragma unroll
            for (int mi = 0; mi < 4; mi++) {
                if (mi < 3) {
                    ldmx4(af[(mi + 1) & 1], sA + swz(arow[mi + 1] + kbo));
                } else if (ks < 3) {
                    loadB(sB, kbo + 32, bf[cur ^ 1]);
                    ldmx4(af[0], sA + swz(arow[0] + kbo + 32));
                }
#pragma unroll
                for (int ni = 0; ni < 4; ni++)
                    mma16816(acc[mi][ni], af[mi & 1], bf[cur][ni]);
            }
        }
        cp_wait1();
        __syncthreads();
        if (kt + 1 < KTILES) {
            loadB(ns + TILE_BYTES, 0, bf[0]);
            ldmx4(af[0], ns + swz(arow[0]));
        }
        ls = cs;
        cs = ns;
    }

    // epilogue
    const float is = iscale[0];
    float sc[4][2], bq[4][2];
#pragma unroll
    for (int ni = 0; ni < 4; ni++)
#pragma unroll
        for (int j = 0; j < 2; j++) {
            const int n = n0 + wn + ni * 8 + (lane & 3) * 2 + j;
            const float s = 1.0f / (wscale[n] * is);
            sc[ni][j] = s;
            bq[ni][j] = bias[n] * s;
        }
    const int mrow = m0 + wm + (lane >> 2);
    const int ncol0 = n0 + wn + (lane & 3) * 2;
#pragma unroll
    for (int mi = 0; mi < 4; mi++) {
#pragma unroll
        for (int ni = 0; ni < 4; ni++) {
            float* o0 = out + (size_t)(mrow + mi * 16) * DOUT + ncol0 + ni * 8;
            float* o1 = o0 + 8 * DOUT;
            float2 v0, v1;
            v0.x = acc[mi][ni][0] * sc[ni][0] + bq[ni][0];
            v0.y = acc[mi][ni][1] * sc[ni][1] + bq[ni][1];
            v1.x = acc[mi][ni][2] * sc[ni][0] + bq[ni][0];
            v1.y = acc[mi][ni][3] * sc[ni][1] + bq[ni][1];
            *reinterpret_cast<float2*>(o0) = v0;
            *reinterpret_cast<float2*>(o1) = v1;
        }
    }
}

// ---------- launch ----------
extern "C" void kernel_launch(void* const* d_in, const int* in_sizes, int n_in,
                              void* d_out, int out_size) {
    const float* x  = (const float*)d_in[0];
    const float* w  = (const float*)d_in[1];
    const float* bi = (const float*)d_in[2];
    const float* ws = (const float*)d_in[3];
    const float* is = (const float*)d_in[4];
    float* out = (float*)d_out;

    cudaFuncSetAttribute(gemm_kernel,
                         cudaFuncAttributeMaxDynamicSharedMemorySize, SMEM_TOTAL);

    quant_kernel<<<NXB + NWB, 256>>>(x, w, ws, is);
    gemm_kernel<<<dim3(DOUT / BN, MROWS / BM), 256, SMEM_TOTAL>>>(bi, ws, is, out);
}